// round 2
// baseline (speedup 1.0000x reference)
#include <cuda_runtime.h>
#include <cuda_bf16.h>
#include <cstdint>
#include <cstdio>

// Problem constants
#define BB 8
#define PP 16
#define SS 512
#define DD 512
#define HH 8
#define DEPTH 64
#define DFF 2048
#define VOC 10000
#define NROW 128              // B*P
#define SIGMA 0.1f
#define LN_EPS 1e-6f

// Output offsets (float elements), reference return order:
// r4, z, avg_pred_after_softmax, good_avg_pred, max_prediction, eps_z,
// attn_weights, K, Vs, w_new, I_new
static const size_t OFF_R4    = 0;
static const size_t OFF_Z     = 65536;
static const size_t OFF_AVGS  = 131072;
static const size_t OFF_GAVG  = 211072;
static const size_t OFF_MAXP  = 291072;
static const size_t OFF_EPSZ  = 371072;
static const size_t OFF_ATTNW = 436608;
static const size_t OFF_K     = 502144;
static const size_t OFF_V     = 502144ULL + 33554432ULL;       // 34056576
static const size_t OFF_WNEW  = 67611008ULL;
static const size_t OFF_INEW  = 67611136ULL;

// ---------------- device scratch ----------------
__device__ float g_q[NROW * DD];
__device__ float g_k[NROW * DD];
__device__ float g_v[NROW * DD];
__device__ float g_zattn[NROW * DD];
__device__ float g_z[NROW * DD];
__device__ float g_out1[NROW * DD];
__device__ float g_h[NROW * DFF];
__device__ float g_f[NROW * DD];
__device__ float g_rr[NROW * DD];
__device__ float g_pred[NROW * VOC];
__device__ float g_rowmax[NROW];
__device__ float g_rowrsum[NROW];
__device__ float g_wsq[NROW];
__device__ int   g_it[NROW];
__device__ int   g_argmax[BB];

// ---------------- GEMM: C[M,N] = A[M,K] @ W[K,N] + bias (+ eps / relu) ------
struct GArgs {
    const float* A;
    const float* W;
    const float* bias;
    const float* eps;   // used when mode==1
    float* C;
};

#define GM 64
#define GN 64
#define GK 32

__global__ __launch_bounds__(256)
void gemm_kernel(GArgs g0, GArgs g1, GArgs g2, int M, int N, int K, int mode) {
    GArgs g = (blockIdx.z == 0) ? g0 : (blockIdx.z == 1) ? g1 : g2;
    __shared__ float As[GM][GK];
    __shared__ float Ws[GK][GN];
    int tid = threadIdx.x;
    int tx = tid & 15, ty = tid >> 4;
    int m0 = blockIdx.y * GM;
    int n0 = blockIdx.x * GN;

    float acc[4][4];
#pragma unroll
    for (int i = 0; i < 4; i++)
#pragma unroll
        for (int j = 0; j < 4; j++) acc[i][j] = 0.0f;

    int arow = tid >> 3, akq = tid & 7;   // A tile: 32 rows per half x 8 quads
    int wkk = tid >> 4, wnq = tid & 15;   // W tile: 16 kk x 16 quads (x2 halves)

    for (int k0 = 0; k0 < K; k0 += GK) {
        // A tile: 64 rows x 32 cols = 2048 floats = 512 float4; 256 threads x 2
        {
            float4 av0 = *(const float4*)&g.A[(size_t)(m0 + arow) * K + k0 + akq * 4];
            *(float4*)&As[arow][akq * 4] = av0;
            float4 av1 = *(const float4*)&g.A[(size_t)(m0 + 32 + arow) * K + k0 + akq * 4];
            *(float4*)&As[32 + arow][akq * 4] = av1;
        }
        // W tile: 32 kk x 64 cols = 2048 floats = 512 float4; 256 threads x 2
        {
            int ncol = n0 + wnq * 4;
            float4 wv0 = make_float4(0.f, 0.f, 0.f, 0.f);
            float4 wv1 = make_float4(0.f, 0.f, 0.f, 0.f);
            if (ncol < N) {
                wv0 = *(const float4*)&g.W[(size_t)(k0 + wkk) * N + ncol];
                wv1 = *(const float4*)&g.W[(size_t)(k0 + 16 + wkk) * N + ncol];
            }
            *(float4*)&Ws[wkk][wnq * 4] = wv0;
            *(float4*)&Ws[16 + wkk][wnq * 4] = wv1;
        }
        __syncthreads();
#pragma unroll
        for (int kk = 0; kk < GK; kk++) {
            float a[4], b[4];
#pragma unroll
            for (int i = 0; i < 4; i++) a[i] = As[ty * 4 + i][kk];
#pragma unroll
            for (int j = 0; j < 4; j++) b[j] = Ws[kk][tx * 4 + j];
#pragma unroll
            for (int i = 0; i < 4; i++)
#pragma unroll
                for (int j = 0; j < 4; j++) acc[i][j] += a[i] * b[j];
        }
        __syncthreads();
    }

#pragma unroll
    for (int i = 0; i < 4; i++) {
        int row = m0 + ty * 4 + i;
#pragma unroll
        for (int j = 0; j < 4; j++) {
            int col = n0 + tx * 4 + j;
            if (col < N) {
                float v = acc[i][j] + g.bias[col];
                if (mode == 1) v += SIGMA * g.eps[(size_t)row * N + col];
                if (mode == 2) v = fmaxf(v, 0.0f);
                g.C[(size_t)row * N + col] = v;
            }
        }
    }
}

// ---------------- attention ----------------
// one block per (b,p). scores over s in [0,t], softmax per head, weighted V sum.
__global__ __launch_bounds__(256)
void attn_kernel(const float* __restrict__ Kin, const float* __restrict__ Vin,
                 float* __restrict__ attnw, const int* __restrict__ tptr) {
    int t = *tptr;
    int tlen = t + 1;
    if (tlen > SS) tlen = SS;
    int bp = blockIdx.x;
    int tid = threadIdx.x;

    __shared__ float qs[DD];
    __shared__ float sc[HH][SS + 8];

    qs[tid] = g_q[bp * DD + tid];
    qs[tid + 256] = g_q[bp * DD + 256 + tid];
    __syncthreads();

    // scores
    for (int idx = tid; idx < HH * tlen; idx += 256) {
        int h = idx / tlen;
        int s = idx - h * tlen;
        const float* kr = (s == t) ? &g_k[bp * DD]
                                   : &Kin[((size_t)bp * SS + s) * DD];
        const float4* k4 = (const float4*)(kr + h * DEPTH);
        const float4* q4 = (const float4*)(qs + h * DEPTH);
        float acc = 0.0f;
#pragma unroll
        for (int i = 0; i < DEPTH / 4; i++) {
            float4 kv = k4[i], qv = q4[i];
            acc += kv.x * qv.x + kv.y * qv.y + kv.z * qv.z + kv.w * qv.w;
        }
        sc[h][s] = acc * 0.125f;   // 1/sqrt(64)
    }
    __syncthreads();

    // softmax: warp w handles head w
    int wid = tid >> 5, lane = tid & 31;
    {
        float mx = -1e30f;
        for (int s = lane; s < tlen; s += 32) mx = fmaxf(mx, sc[wid][s]);
#pragma unroll
        for (int o = 16; o; o >>= 1) mx = fmaxf(mx, __shfl_xor_sync(~0u, mx, o));
        float sum = 0.0f;
        for (int s = lane; s < tlen; s += 32) {
            float e = __expf(sc[wid][s] - mx);
            sc[wid][s] = e;
            sum += e;
        }
#pragma unroll
        for (int o = 16; o; o >>= 1) sum += __shfl_xor_sync(~0u, sum, o);
        float r = 1.0f / sum;
        for (int s = lane; s < tlen; s += 32) sc[wid][s] *= r;
    }
    __syncthreads();

    // attn_weights = mean over heads; zero for masked positions
    for (int s = tid; s < SS; s += 256) {
        float v = 0.0f;
        if (s < tlen) {
#pragma unroll
            for (int h = 0; h < HH; h++) v += sc[h][s];
            v *= (1.0f / HH);
        }
        attnw[(size_t)bp * SS + s] = v;
    }

    // z = attn @ V
    int d0 = tid, d1 = tid + 256;
    int h0 = d0 >> 6, h1 = d1 >> 6;
    float acc0 = 0.0f, acc1 = 0.0f;
#pragma unroll 4
    for (int s = 0; s < tlen; s++) {
        const float* vr = (s == t) ? &g_v[bp * DD]
                                   : &Vin[((size_t)bp * SS + s) * DD];
        acc0 += sc[h0][s] * vr[d0];
        acc1 += sc[h1][s] * vr[d1];
    }
    g_zattn[bp * DD + d0] = acc0;
    g_zattn[bp * DD + d1] = acc1;
}

// ---------------- layernorm: out = LN(a + add) * gam + bet ----------------
__global__ __launch_bounds__(256)
void ln_kernel(const float* __restrict__ a, const float* __restrict__ add,
               const float* __restrict__ gam, const float* __restrict__ bet,
               float* __restrict__ out) {
    int row = blockIdx.x;
    int tid = threadIdx.x;
    __shared__ float sh[8];
    __shared__ float s_mu, s_inv;

    float x0 = a[row * DD + tid] + add[row * DD + tid];
    float x1 = a[row * DD + 256 + tid] + add[row * DD + 256 + tid];
    float s = x0 + x1;
    float sq = x0 * x0 + x1 * x1;
#pragma unroll
    for (int o = 16; o; o >>= 1) {
        s  += __shfl_xor_sync(~0u, s, o);
        sq += __shfl_xor_sync(~0u, sq, o);
    }
    if ((tid & 31) == 0) sh[tid >> 5] = s;
    __syncthreads();
    if (tid == 0) {
        float t = 0;
        for (int i = 0; i < 8; i++) t += sh[i];
        s_mu = t / DD;
    }
    __syncthreads();
    if ((tid & 31) == 0) sh[tid >> 5] = sq;
    __syncthreads();
    if (tid == 0) {
        float t = 0;
        for (int i = 0; i < 8; i++) t += sh[i];
        float var = t / DD - s_mu * s_mu;
        s_inv = rsqrtf(var + LN_EPS);
    }
    __syncthreads();
    float mu = s_mu, inv = s_inv;
    out[row * DD + tid]       = (x0 - mu) * inv * gam[tid] + bet[tid];
    out[row * DD + 256 + tid] = (x1 - mu) * inv * gam[tid + 256] + bet[tid + 256];
}

// ---------------- per-row softmax stats over VOC ----------------
__global__ __launch_bounds__(256)
void rowsoftmax_kernel(const int* __restrict__ x, float* __restrict__ wnew) {
    int row = blockIdx.x;
    const float* pr = g_pred + (size_t)row * VOC;
    int tid = threadIdx.x;
    __shared__ float sh[8];
    __shared__ float s_mx;

    float mx = -1e30f;
    for (int c = tid; c < VOC; c += 256) mx = fmaxf(mx, pr[c]);
#pragma unroll
    for (int o = 16; o; o >>= 1) mx = fmaxf(mx, __shfl_xor_sync(~0u, mx, o));
    if ((tid & 31) == 0) sh[tid >> 5] = mx;
    __syncthreads();
    if (tid == 0) {
        float m = sh[0];
        for (int i = 1; i < 8; i++) m = fmaxf(m, sh[i]);
        s_mx = m;
    }
    __syncthreads();
    mx = s_mx;
    float sum = 0.0f;
    for (int c = tid; c < VOC; c += 256) sum += __expf(pr[c] - mx);
#pragma unroll
    for (int o = 16; o; o >>= 1) sum += __shfl_xor_sync(~0u, sum, o);
    __syncthreads();
    if ((tid & 31) == 0) sh[tid >> 5] = sum;
    __syncthreads();
    if (tid == 0) {
        float sm = 0;
        for (int i = 0; i < 8; i++) sm += sh[i];
        g_rowmax[row] = mx;
        g_rowrsum[row] = 1.0f / sm;
        int b = row >> 4;
        float w = __expf(pr[x[b]] - mx) / sm;
        g_wsq[row] = w;
        wnew[row] = w;
    }
}

// ---------------- particle step: argmax_w per b, gumbel i_t ----------------
__global__ __launch_bounds__(128)
void particle_kernel(const float* __restrict__ gumbel) {
    int tid = threadIdx.x;   // 0..127 == b*16+p
    int b = tid >> 4, p = tid & 15;
    __shared__ float lw[NROW];
    lw[tid] = logf(g_wsq[tid] + 1e-10f);
    __syncthreads();
    float best = -1e38f;
    int arg = 0;
    for (int j = 0; j < PP; j++) {
        float v = lw[b * PP + j] + gumbel[(b * PP + p) * PP + j];
        if (v > best) { best = v; arg = j; }
    }
    g_it[tid] = arg;
    if (p == 0) {
        float bw = g_wsq[b * PP];
        int a = 0;
        for (int j = 1; j < PP; j++)
            if (g_wsq[b * PP + j] > bw) { bw = g_wsq[b * PP + j]; a = j; }
        g_argmax[b] = a;
    }
}

// ---------------- vocab reductions over particles ----------------
__global__ __launch_bounds__(256)
void vocab_reduce_kernel(float* __restrict__ avgs, float* __restrict__ gavg,
                         float* __restrict__ maxp) {
    int b = blockIdx.y;
    int c = blockIdx.x * 256 + threadIdx.x;
    if (c >= VOC) return;
    int am = g_argmax[b];
    float sp = 0.0f, ss = 0.0f, mp = 0.0f;
#pragma unroll
    for (int p = 0; p < PP; p++) {
        int row = b * PP + p;
        float v = g_pred[(size_t)row * VOC + c];
        sp += v;
        ss += __expf(v - g_rowmax[row]) * g_rowrsum[row];
        if (p == am) mp = v;
    }
    __stcs(&gavg[(size_t)b * VOC + c], sp * (1.0f / PP));
    __stcs(&avgs[(size_t)b * VOC + c], ss * (1.0f / PP));
    __stcs(&maxp[(size_t)b * VOC + c], mp);
}

// ---------------- misc copies / gathers ----------------
__global__ __launch_bounds__(256)
void misc_kernel(const float* __restrict__ r, const float* __restrict__ epsz,
                 const int* __restrict__ I, const int* __restrict__ tptr,
                 float* __restrict__ out) {
    int t = *tptr;
    int idx = blockIdx.x * 256 + threadIdx.x;   // 0..65535
    out[OFF_R4 + idx] = r[idx];
    out[OFF_EPSZ + idx] = epsz[idx];
    int row = idx >> 9, d = idx & 511;
    int b = row >> 4;
    int i1 = g_it[row];
    out[OFF_Z + idx] = g_z[(b * PP + i1) * DD + d];
    int s = d;
    int val;
    if (s < t)      val = I[(b * PP + i1) * SS + s];
    else if (s == t) val = i1;
    else            val = I[idx];
    out[OFF_INEW + idx] = (float)val;
}

// ---------------- resample K and Vs (fused) ----------------
// K_new[b,p,s<=t] = K[b,i1,s] (s==t -> g_k[b,i1]); s>t -> K[b,p,s]
// Vs_new[b,p,s<=t] = K[b,i2,s] (s==t -> g_k[b,i2]); s>t -> K[b,p,s]
// where i1 = i_t[b,p], i2 = i_t[b,i1]   (replicates the reference's Vs=resample(K) bug)
__global__ __launch_bounds__(256)
void resample_kernel(const float* __restrict__ Kin, const int* __restrict__ tptr,
                     float* __restrict__ out) {
    int t = *tptr;
    int tid = threadIdx.x;
    int rid = blockIdx.x * 2 + (tid >> 7);  // row id 0..65535 (= bp*512+s)
    int d4 = tid & 127;
    int s = rid & 511;
    int bp = rid >> 9;
    int b = bp >> 4;
    size_t dst = (size_t)rid * DD + d4 * 4;
    if (s > t) {
        float4 v = __ldg(&((const float4*)&Kin[((size_t)bp * SS + s) * DD])[d4]);
        __stcs((float4*)&out[OFF_K + dst], v);
        __stcs((float4*)&out[OFF_V + dst], v);
    } else {
        int i1 = g_it[bp];
        int i2 = g_it[b * PP + i1];
        const float* sk = (s == t) ? &g_k[(b * PP + i1) * DD]
                                   : &Kin[(((size_t)(b * PP + i1)) * SS + s) * DD];
        const float* sv = (s == t) ? &g_k[(b * PP + i2) * DD]
                                   : &Kin[(((size_t)(b * PP + i2)) * SS + s) * DD];
        __stcs((float4*)&out[OFF_K + dst], ((const float4*)sk)[d4]);
        __stcs((float4*)&out[OFF_V + dst], ((const float4*)sv)[d4]);
    }
}

// ---------------- launch ----------------
extern "C" void kernel_launch(void* const* d_in, const int* in_sizes, int n_in,
                              void* d_out, int out_size) {
    (void)in_sizes; (void)n_in; (void)out_size;
    const float* r      = (const float*)d_in[0];
    const int*   x      = (const int*)d_in[1];
    const float* Kin    = (const float*)d_in[2];
    const float* Vin    = (const float*)d_in[3];
    const int*   I      = (const int*)d_in[5];
    const int*   tptr   = (const int*)d_in[6];
    const float* eps_q  = (const float*)d_in[7];
    const float* eps_k  = (const float*)d_in[8];
    const float* eps_v  = (const float*)d_in[9];
    const float* eps_z  = (const float*)d_in[10];
    const float* gumbel = (const float*)d_in[11];
    const float* Wq = (const float*)d_in[12];
    const float* bq = (const float*)d_in[13];
    const float* Wk = (const float*)d_in[14];
    const float* bk = (const float*)d_in[15];
    const float* Wv = (const float*)d_in[16];
    const float* bv = (const float*)d_in[17];
    const float* Wo = (const float*)d_in[18];
    const float* bo = (const float*)d_in[19];
    const float* ln1_g = (const float*)d_in[20];
    const float* ln1_b = (const float*)d_in[21];
    const float* ln3_g = (const float*)d_in[22];
    const float* ln3_b = (const float*)d_in[23];
    const float* W1 = (const float*)d_in[24];
    const float* b1 = (const float*)d_in[25];
    const float* W2 = (const float*)d_in[26];
    const float* b2 = (const float*)d_in[27];
    const float* Wout = (const float*)d_in[28];
    const float* bout = (const float*)d_in[29];
    float* out = (float*)d_out;

    float *p_q, *p_k, *p_v, *p_zattn, *p_z, *p_out1, *p_h, *p_f, *p_rr, *p_pred;
    cudaGetSymbolAddress((void**)&p_q, g_q);
    cudaGetSymbolAddress((void**)&p_k, g_k);
    cudaGetSymbolAddress((void**)&p_v, g_v);
    cudaGetSymbolAddress((void**)&p_zattn, g_zattn);
    cudaGetSymbolAddress((void**)&p_z, g_z);
    cudaGetSymbolAddress((void**)&p_out1, g_out1);
    cudaGetSymbolAddress((void**)&p_h, g_h);
    cudaGetSymbolAddress((void**)&p_f, g_f);
    cudaGetSymbolAddress((void**)&p_rr, g_rr);
    cudaGetSymbolAddress((void**)&p_pred, g_pred);

    // 1. q,k,v projections (+ bias + sigma*eps)
    {
        GArgs gq{r, Wq, bq, eps_q, p_q};
        GArgs gk{r, Wk, bk, eps_k, p_k};
        GArgs gv{r, Wv, bv, eps_v, p_v};
        gemm_kernel<<<dim3(DD / GN, NROW / GM, 3), 256>>>(gq, gk, gv, NROW, DD, DD, 1);
    }
    // 2. attention (writes attn_weights output + g_zattn)
    attn_kernel<<<NROW, 256>>>(Kin, Vin, out + OFF_ATTNW, tptr);
    // 3. z = zattn @ Wo + bo + sigma*eps_z
    {
        GArgs gz{p_zattn, Wo, bo, eps_z, p_z};
        gemm_kernel<<<dim3(DD / GN, NROW / GM, 1), 256>>>(gz, gz, gz, NROW, DD, DD, 1);
    }
    // 4. out1 = LN(z + r)
    ln_kernel<<<NROW, 256>>>(p_z, r, ln1_g, ln1_b, p_out1);
    // 5. h = relu(out1 @ W1 + b1)
    {
        GArgs gf{p_out1, W1, b1, nullptr, p_h};
        gemm_kernel<<<dim3(DFF / GN, NROW / GM, 1), 256>>>(gf, gf, gf, NROW, DFF, DD, 2);
    }
    // 6. f = h @ W2 + b2
    {
        GArgs gf{p_h, W2, b2, nullptr, p_f};
        gemm_kernel<<<dim3(DD / GN, NROW / GM, 1), 256>>>(gf, gf, gf, NROW, DD, DFF, 0);
    }
    // 7. r_ = LN(f + out1)
    ln_kernel<<<NROW, 256>>>(p_f, p_out1, ln3_g, ln3_b, p_rr);
    // 8. predictions = r_ @ Wout + bout
    {
        GArgs gp{p_rr, Wout, bout, nullptr, p_pred};
        gemm_kernel<<<dim3((VOC + GN - 1) / GN, NROW / GM, 1), 256>>>(gp, gp, gp, NROW, VOC, DD, 0);
    }
    // 9. per-row softmax stats + w_sq (writes w_new)
    rowsoftmax_kernel<<<NROW, 256>>>(x, out + OFF_WNEW);
    // 10. argmax_w + gumbel resampling indices
    particle_kernel<<<1, 128>>>(gumbel);
    // 11. vocab reductions (avg softmax, avg pred, max pred)
    vocab_reduce_kernel<<<dim3((VOC + 255) / 256, BB), 256>>>(
        out + OFF_AVGS, out + OFF_GAVG, out + OFF_MAXP);
    // 12. misc copies + gathers (r4, eps_z, z gather, I_new)
    misc_kernel<<<NROW * DD / 256, 256>>>(r, eps_z, I, tptr, out);
    // 13. resample K and Vs (big copy)
    resample_kernel<<<NROW * SS / 2, 256>>>(Kin, tptr, out);
}

// round 5
// speedup vs baseline: 1.2749x; 1.2749x over previous
#include <cuda_runtime.h>
#include <cuda_bf16.h>
#include <cstdint>
#include <cstdio>

// Problem constants
#define BB 8
#define PP 16
#define SS 512
#define DD 512
#define HH 8
#define DEPTH 64
#define DFF 2048
#define VOC 10000
#define NROW 128              // B*P
#define SIGMA 0.1f
#define LN_EPS 1e-6f

// Output offsets (float elements)
static const size_t OFF_R4    = 0;
static const size_t OFF_Z     = 65536;
static const size_t OFF_AVGS  = 131072;
static const size_t OFF_GAVG  = 211072;
static const size_t OFF_MAXP  = 291072;
static const size_t OFF_EPSZ  = 371072;
static const size_t OFF_ATTNW = 436608;
static const size_t OFF_K     = 502144;
static const size_t OFF_V     = 502144ULL + 33554432ULL;
static const size_t OFF_WNEW  = 67611008ULL;
static const size_t OFF_INEW  = 67611136ULL;

// ---------------- device scratch ----------------
__device__ float g_q[NROW * DD];
__device__ float g_k[NROW * DD];
__device__ float g_v[NROW * DD];
__device__ float g_zattn[NROW * DD];
__device__ float g_z[NROW * DD];
__device__ float g_out1[NROW * DD];
__device__ float g_h[NROW * DFF];
__device__ float g_rr[NROW * DD];
__device__ float g_pred[NROW * VOC];
__device__ float g_part[3 * 4 * NROW * DD * 4];   // partial buffer
__device__ float g_rowmax[NROW];
__device__ float g_rowrsum[NROW];
__device__ float g_wsq[NROW];
__device__ int   g_it[NROW];
__device__ int   g_argmax[BB];

// ---------------- packed f32x2 helpers ----------------
union F2U { float2 f; unsigned long long u; };

__device__ __forceinline__ unsigned long long fma2(unsigned long long a,
                                                   unsigned long long b,
                                                   unsigned long long c) {
    unsigned long long d;
    asm("fma.rn.f32x2 %0, %1, %2, %3;" : "=l"(d) : "l"(a), "l"(b), "l"(c));
    return d;
}

// ---------------- GEMM v2 ----------------
// C[M,N] = A[M,K] @ W[K,N]. Split-K over blockIdx.z; up to 3 fused GEMM instances.
// ksplit==1 -> direct write with bias/eps/relu; else raw partial into part[].
struct GArgs {
    const float* A;
    const float* W;
    const float* bias;
    const float* eps;
    float* C;
};

#define GM 64
#define GN 64
#define GK 32

__global__ __launch_bounds__(256)
void gemm2_kernel(GArgs g0, GArgs g1, GArgs g2, int M, int N, int K,
                  int ksplit, int klen, int mode, float* part) {
    int z = blockIdx.z;
    int gi = z / ksplit, kz = z - gi * ksplit;
    GArgs g = (gi == 0) ? g0 : (gi == 1) ? g1 : g2;

    __shared__ float2 As2[GK][GM];      // duplicated: {a,a}
    __shared__ float  Ws[GK][GN];

    int tid = threadIdx.x;
    int tx = tid & 15, ty = tid >> 4;
    int m0 = blockIdx.y * GM;
    int n0 = blockIdx.x * GN;
    int kbase = kz * klen;

    unsigned long long acc[4][2];
#pragma unroll
    for (int i = 0; i < 4; i++) { acc[i][0] = 0ULL; acc[i][1] = 0ULL; }

    int arow = tid >> 3, akq = tid & 7;   // A loader: rows 0..31 (+32), 8 k-quads
    int wkk = tid >> 4, wnq = tid & 15;   // W loader: 16 k (+16), 16 n-quads

    for (int k0 = 0; k0 < klen; k0 += GK) {
        // A tile -> transposed + duplicated
        {
            float4 av0 = *(const float4*)&g.A[(size_t)(m0 + arow) * K + kbase + k0 + akq * 4];
            float4 av1 = *(const float4*)&g.A[(size_t)(m0 + 32 + arow) * K + kbase + k0 + akq * 4];
            As2[akq * 4 + 0][arow] = make_float2(av0.x, av0.x);
            As2[akq * 4 + 1][arow] = make_float2(av0.y, av0.y);
            As2[akq * 4 + 2][arow] = make_float2(av0.z, av0.z);
            As2[akq * 4 + 3][arow] = make_float2(av0.w, av0.w);
            As2[akq * 4 + 0][arow + 32] = make_float2(av1.x, av1.x);
            As2[akq * 4 + 1][arow + 32] = make_float2(av1.y, av1.y);
            As2[akq * 4 + 2][arow + 32] = make_float2(av1.z, av1.z);
            As2[akq * 4 + 3][arow + 32] = make_float2(av1.w, av1.w);
        }
        // W tile
        {
            int ncol = n0 + wnq * 4;
            float4 wv0 = make_float4(0.f, 0.f, 0.f, 0.f);
            float4 wv1 = make_float4(0.f, 0.f, 0.f, 0.f);
            if (ncol < N) {
                wv0 = *(const float4*)&g.W[(size_t)(kbase + k0 + wkk) * N + ncol];
                wv1 = *(const float4*)&g.W[(size_t)(kbase + k0 + 16 + wkk) * N + ncol];
            }
            *(float4*)&Ws[wkk][wnq * 4] = wv0;
            *(float4*)&Ws[16 + wkk][wnq * 4] = wv1;
        }
        __syncthreads();
#pragma unroll
        for (int kk = 0; kk < GK; kk++) {
            F2U a0, a1, a2, a3, b0, b1;
            a0.f = As2[kk][ty * 4 + 0];
            a1.f = As2[kk][ty * 4 + 1];
            a2.f = As2[kk][ty * 4 + 2];
            a3.f = As2[kk][ty * 4 + 3];
            b0.f = *(const float2*)&Ws[kk][tx * 4];
            b1.f = *(const float2*)&Ws[kk][tx * 4 + 2];
            acc[0][0] = fma2(a0.u, b0.u, acc[0][0]);
            acc[0][1] = fma2(a0.u, b1.u, acc[0][1]);
            acc[1][0] = fma2(a1.u, b0.u, acc[1][0]);
            acc[1][1] = fma2(a1.u, b1.u, acc[1][1]);
            acc[2][0] = fma2(a2.u, b0.u, acc[2][0]);
            acc[2][1] = fma2(a2.u, b1.u, acc[2][1]);
            acc[3][0] = fma2(a3.u, b0.u, acc[3][0]);
            acc[3][1] = fma2(a3.u, b1.u, acc[3][1]);
        }
        __syncthreads();
    }

    if (ksplit > 1) {
        float* P = part + (size_t)(gi * ksplit + kz) * M * N;
#pragma unroll
        for (int i = 0; i < 4; i++) {
            int row = m0 + ty * 4 + i;
#pragma unroll
            for (int jp = 0; jp < 2; jp++) {
                int col = n0 + tx * 4 + jp * 2;
                F2U t; t.u = acc[i][jp];
                if (col < N)     P[(size_t)row * N + col] = t.f.x;
                if (col + 1 < N) P[(size_t)row * N + col + 1] = t.f.y;
            }
        }
    } else {
#pragma unroll
        for (int i = 0; i < 4; i++) {
            int row = m0 + ty * 4 + i;
#pragma unroll
            for (int jp = 0; jp < 2; jp++) {
                int col = n0 + tx * 4 + jp * 2;
                F2U t; t.u = acc[i][jp];
                float vx = t.f.x, vy = t.f.y;
                if (col < N) {
                    float v = vx + g.bias[col];
                    if (mode == 1) v += SIGMA * g.eps[(size_t)row * N + col];
                    if (mode == 2) v = fmaxf(v, 0.0f);
                    g.C[(size_t)row * N + col] = v;
                }
                if (col + 1 < N) {
                    float v = vy + g.bias[col + 1];
                    if (mode == 1) v += SIGMA * g.eps[(size_t)row * N + col + 1];
                    if (mode == 2) v = fmaxf(v, 0.0f);
                    g.C[(size_t)row * N + col + 1] = v;
                }
            }
        }
    }
}

// ---------------- epilogue: sum partials + bias (+eps / relu) ----------------
struct EArgs { const float* bias; const float* eps; float* C; };

__global__ __launch_bounds__(256)
void epi_simple_kernel(EArgs e0, EArgs e1, EArgs e2, int N, int MN,
                       int ksplit, int mode, const float* part) {
    int gi = blockIdx.y;
    EArgs e = (gi == 0) ? e0 : (gi == 1) ? e1 : e2;
    int idx = blockIdx.x * 256 + threadIdx.x;
    if (idx >= MN) return;
    int col = idx % N;
    float v = e.bias[col];
    const float* P = part + (size_t)gi * ksplit * MN + idx;
    for (int kz = 0; kz < ksplit; kz++) v += P[(size_t)kz * MN];
    if (mode == 1) v += SIGMA * e.eps[idx];
    if (mode == 2) v = fmaxf(v, 0.0f);
    e.C[idx] = v;
}

// ---------------- epilogue with fused LayerNorm (N = DD = 512) ----------------
__global__ __launch_bounds__(256)
void epi_ln_kernel(const float* part, int ksplit,
                   const float* __restrict__ bias, const float* __restrict__ eps,
                   const float* __restrict__ add, const float* __restrict__ gam,
                   const float* __restrict__ bet, float* __restrict__ mid,
                   float* __restrict__ out) {
    int row = blockIdx.x;
    int tid = threadIdx.x;
    __shared__ float sh[8];
    __shared__ float s_mu, s_inv;

    int c0 = tid, c1 = tid + 256;
    float v0 = bias[c0], v1 = bias[c1];
    for (int kz = 0; kz < ksplit; kz++) {
        const float* P = part + (size_t)kz * NROW * DD + (size_t)row * DD;
        v0 += P[c0];
        v1 += P[c1];
    }
    if (eps) {
        v0 += SIGMA * eps[(size_t)row * DD + c0];
        v1 += SIGMA * eps[(size_t)row * DD + c1];
    }
    if (mid) {
        mid[(size_t)row * DD + c0] = v0;
        mid[(size_t)row * DD + c1] = v1;
    }
    float x0 = v0 + add[(size_t)row * DD + c0];
    float x1 = v1 + add[(size_t)row * DD + c1];

    float s = x0 + x1;
    float sq = x0 * x0 + x1 * x1;
#pragma unroll
    for (int o = 16; o; o >>= 1) {
        s  += __shfl_xor_sync(~0u, s, o);
        sq += __shfl_xor_sync(~0u, sq, o);
    }
    if ((tid & 31) == 0) sh[tid >> 5] = s;
    __syncthreads();
    if (tid == 0) {
        float t = 0;
        for (int i = 0; i < 8; i++) t += sh[i];
        s_mu = t / DD;
    }
    __syncthreads();
    if ((tid & 31) == 0) sh[tid >> 5] = sq;
    __syncthreads();
    if (tid == 0) {
        float t = 0;
        for (int i = 0; i < 8; i++) t += sh[i];
        float var = t / DD - s_mu * s_mu;
        s_inv = rsqrtf(var + LN_EPS);
    }
    __syncthreads();
    float mu = s_mu, inv = s_inv;
    out[(size_t)row * DD + c0] = (x0 - mu) * inv * gam[c0] + bet[c0];
    out[(size_t)row * DD + c1] = (x1 - mu) * inv * gam[c1] + bet[c1];
}

// ---------------- attention ----------------
__global__ __launch_bounds__(256)
void attn_kernel(const float* __restrict__ Kin, const float* __restrict__ Vin,
                 float* __restrict__ attnw, const int* __restrict__ tptr) {
    int t = *tptr;
    int tlen = t + 1;
    if (tlen > SS) tlen = SS;
    int bp = blockIdx.x;
    int tid = threadIdx.x;

    __shared__ float qs[DD];
    __shared__ float sc[HH][SS + 8];

    qs[tid] = g_q[bp * DD + tid];
    qs[tid + 256] = g_q[bp * DD + 256 + tid];
    __syncthreads();

    for (int idx = tid; idx < HH * tlen; idx += 256) {
        int h = idx / tlen;
        int s = idx - h * tlen;
        const float* kr = (s == t) ? &g_k[bp * DD]
                                   : &Kin[((size_t)bp * SS + s) * DD];
        const float4* k4 = (const float4*)(kr + h * DEPTH);
        const float4* q4 = (const float4*)(qs + h * DEPTH);
        float acc = 0.0f;
#pragma unroll
        for (int i = 0; i < DEPTH / 4; i++) {
            float4 kv = k4[i], qv = q4[i];
            acc += kv.x * qv.x + kv.y * qv.y + kv.z * qv.z + kv.w * qv.w;
        }
        sc[h][s] = acc * 0.125f;
    }
    __syncthreads();

    int wid = tid >> 5, lane = tid & 31;
    {
        float mx = -1e30f;
        for (int s = lane; s < tlen; s += 32) mx = fmaxf(mx, sc[wid][s]);
#pragma unroll
        for (int o = 16; o; o >>= 1) mx = fmaxf(mx, __shfl_xor_sync(~0u, mx, o));
        float sum = 0.0f;
        for (int s = lane; s < tlen; s += 32) {
            float e = __expf(sc[wid][s] - mx);
            sc[wid][s] = e;
            sum += e;
        }
#pragma unroll
        for (int o = 16; o; o >>= 1) sum += __shfl_xor_sync(~0u, sum, o);
        float r = 1.0f / sum;
        for (int s = lane; s < tlen; s += 32) sc[wid][s] *= r;
    }
    __syncthreads();

    for (int s = tid; s < SS; s += 256) {
        float v = 0.0f;
        if (s < tlen) {
#pragma unroll
            for (int h = 0; h < HH; h++) v += sc[h][s];
            v *= (1.0f / HH);
        }
        attnw[(size_t)bp * SS + s] = v;
    }

    int d0 = tid, d1 = tid + 256;
    int h0 = d0 >> 6, h1 = d1 >> 6;
    float acc0 = 0.0f, acc1 = 0.0f;
#pragma unroll 4
    for (int s = 0; s < tlen; s++) {
        const float* vr = (s == t) ? &g_v[bp * DD]
                                   : &Vin[((size_t)bp * SS + s) * DD];
        acc0 += sc[h0][s] * vr[d0];
        acc1 += sc[h1][s] * vr[d1];
    }
    g_zattn[bp * DD + d0] = acc0;
    g_zattn[bp * DD + d1] = acc1;
}

// ---------------- per-row softmax stats over VOC ----------------
__global__ __launch_bounds__(256)
void rowsoftmax_kernel(const int* __restrict__ x, float* __restrict__ wnew) {
    int row = blockIdx.x;
    const float* pr = g_pred + (size_t)row * VOC;
    int tid = threadIdx.x;
    __shared__ float sh[8];
    __shared__ float s_mx;

    float mx = -1e30f;
    for (int c = tid; c < VOC; c += 256) mx = fmaxf(mx, pr[c]);
#pragma unroll
    for (int o = 16; o; o >>= 1) mx = fmaxf(mx, __shfl_xor_sync(~0u, mx, o));
    if ((tid & 31) == 0) sh[tid >> 5] = mx;
    __syncthreads();
    if (tid == 0) {
        float m = sh[0];
        for (int i = 1; i < 8; i++) m = fmaxf(m, sh[i]);
        s_mx = m;
    }
    __syncthreads();
    mx = s_mx;
    float sum = 0.0f;
    for (int c = tid; c < VOC; c += 256) sum += __expf(pr[c] - mx);
#pragma unroll
    for (int o = 16; o; o >>= 1) sum += __shfl_xor_sync(~0u, sum, o);
    __syncthreads();
    if ((tid & 31) == 0) sh[tid >> 5] = sum;
    __syncthreads();
    if (tid == 0) {
        float sm = 0;
        for (int i = 0; i < 8; i++) sm += sh[i];
        g_rowmax[row] = mx;
        g_rowrsum[row] = 1.0f / sm;
        int b = row >> 4;
        float w = __expf(pr[x[b]] - mx) / sm;
        g_wsq[row] = w;
        wnew[row] = w;
    }
}

// ---------------- particle step ----------------
__global__ __launch_bounds__(128)
void particle_kernel(const float* __restrict__ gumbel) {
    int tid = threadIdx.x;
    int b = tid >> 4, p = tid & 15;
    __shared__ float lw[NROW];
    lw[tid] = logf(g_wsq[tid] + 1e-10f);
    __syncthreads();
    float best = -1e38f;
    int arg = 0;
    for (int j = 0; j < PP; j++) {
        float v = lw[b * PP + j] + gumbel[(b * PP + p) * PP + j];
        if (v > best) { best = v; arg = j; }
    }
    g_it[tid] = arg;
    if (p == 0) {
        float bw = g_wsq[b * PP];
        int a = 0;
        for (int j = 1; j < PP; j++)
            if (g_wsq[b * PP + j] > bw) { bw = g_wsq[b * PP + j]; a = j; }
        g_argmax[b] = a;
    }
}

// ---------------- vocab reductions ----------------
__global__ __launch_bounds__(256)
void vocab_reduce_kernel(float* __restrict__ avgs, float* __restrict__ gavg,
                         float* __restrict__ maxp) {
    int b = blockIdx.y;
    int c = blockIdx.x * 256 + threadIdx.x;
    if (c >= VOC) return;
    int am = g_argmax[b];
    float sp = 0.0f, ss = 0.0f, mp = 0.0f;
#pragma unroll
    for (int p = 0; p < PP; p++) {
        int row = b * PP + p;
        float v = g_pred[(size_t)row * VOC + c];
        sp += v;
        ss += __expf(v - g_rowmax[row]) * g_rowrsum[row];
        if (p == am) mp = v;
    }
    __stcs(&gavg[(size_t)b * VOC + c], sp * (1.0f / PP));
    __stcs(&avgs[(size_t)b * VOC + c], ss * (1.0f / PP));
    __stcs(&maxp[(size_t)b * VOC + c], mp);
}

// ---------------- misc copies / gathers ----------------
__global__ __launch_bounds__(256)
void misc_kernel(const float* __restrict__ r, const float* __restrict__ epsz,
                 const int* __restrict__ I, const int* __restrict__ tptr,
                 float* __restrict__ out) {
    int t = *tptr;
    int idx = blockIdx.x * 256 + threadIdx.x;
    out[OFF_R4 + idx] = r[idx];
    out[OFF_EPSZ + idx] = epsz[idx];
    int row = idx >> 9, d = idx & 511;
    int b = row >> 4;
    int i1 = g_it[row];
    out[OFF_Z + idx] = g_z[(b * PP + i1) * DD + d];
    int s = d;
    int val;
    if (s < t)      val = I[(b * PP + i1) * SS + s];
    else if (s == t) val = i1;
    else            val = I[idx];
    out[OFF_INEW + idx] = (float)val;
}

// ---------------- resample K and Vs (fused) ----------------
__global__ __launch_bounds__(256)
void resample_kernel(const float* __restrict__ Kin, const int* __restrict__ tptr,
                     float* __restrict__ out) {
    int t = *tptr;
    int tid = threadIdx.x;
    int rid = blockIdx.x * 2 + (tid >> 7);
    int d4 = tid & 127;
    int s = rid & 511;
    int bp = rid >> 9;
    int b = bp >> 4;
    size_t dst = (size_t)rid * DD + d4 * 4;
    if (s > t) {
        float4 v = __ldg(&((const float4*)&Kin[((size_t)bp * SS + s) * DD])[d4]);
        __stcs((float4*)&out[OFF_K + dst], v);
        __stcs((float4*)&out[OFF_V + dst], v);
    } else {
        int i1 = g_it[bp];
        int i2 = g_it[b * PP + i1];
        const float* sk = (s == t) ? &g_k[(b * PP + i1) * DD]
                                   : &Kin[(((size_t)(b * PP + i1)) * SS + s) * DD];
        const float* sv = (s == t) ? &g_k[(b * PP + i2) * DD]
                                   : &Kin[(((size_t)(b * PP + i2)) * SS + s) * DD];
        __stcs((float4*)&out[OFF_K + dst], ((const float4*)sk)[d4]);
        __stcs((float4*)&out[OFF_V + dst], ((const float4*)sv)[d4]);
    }
}

// ---------------- launch ----------------
extern "C" void kernel_launch(void* const* d_in, const int* in_sizes, int n_in,
                              void* d_out, int out_size) {
    (void)in_sizes; (void)n_in; (void)out_size;
    const float* r      = (const float*)d_in[0];
    const int*   x      = (const int*)d_in[1];
    const float* Kin    = (const float*)d_in[2];
    const float* Vin    = (const float*)d_in[3];
    const int*   I      = (const int*)d_in[5];
    const int*   tptr   = (const int*)d_in[6];
    const float* eps_q  = (const float*)d_in[7];
    const float* eps_k  = (const float*)d_in[8];
    const float* eps_v  = (const float*)d_in[9];
    const float* eps_z  = (const float*)d_in[10];
    const float* gumbel = (const float*)d_in[11];
    const float* Wq = (const float*)d_in[12];
    const float* bq = (const float*)d_in[13];
    const float* Wk = (const float*)d_in[14];
    const float* bk = (const float*)d_in[15];
    const float* Wv = (const float*)d_in[16];
    const float* bv = (const float*)d_in[17];
    const float* Wo = (const float*)d_in[18];
    const float* bo = (const float*)d_in[19];
    const float* ln1_g = (const float*)d_in[20];
    const float* ln1_b = (const float*)d_in[21];
    const float* ln3_g = (const float*)d_in[22];
    const float* ln3_b = (const float*)d_in[23];
    const float* W1 = (const float*)d_in[24];
    const float* b1 = (const float*)d_in[25];
    const float* W2 = (const float*)d_in[26];
    const float* b2 = (const float*)d_in[27];
    const float* Wout = (const float*)d_in[28];
    const float* bout = (const float*)d_in[29];
    float* out = (float*)d_out;

    float *p_q, *p_k, *p_v, *p_zattn, *p_z, *p_out1, *p_h, *p_rr, *p_pred, *p_part;
    cudaGetSymbolAddress((void**)&p_q, g_q);
    cudaGetSymbolAddress((void**)&p_k, g_k);
    cudaGetSymbolAddress((void**)&p_v, g_v);
    cudaGetSymbolAddress((void**)&p_zattn, g_zattn);
    cudaGetSymbolAddress((void**)&p_z, g_z);
    cudaGetSymbolAddress((void**)&p_out1, g_out1);
    cudaGetSymbolAddress((void**)&p_h, g_h);
    cudaGetSymbolAddress((void**)&p_rr, g_rr);
    cudaGetSymbolAddress((void**)&p_pred, g_pred);
    cudaGetSymbolAddress((void**)&p_part, g_part);

    GArgs gz0{nullptr, nullptr, nullptr, nullptr, nullptr};

    // 1. q,k,v projections: split-K 4 -> partials, then epilogue (+bias +eps)
    {
        GArgs gq{r, Wq, bq, eps_q, p_q};
        GArgs gk{r, Wk, bk, eps_k, p_k};
        GArgs gv{r, Wv, bv, eps_v, p_v};
        gemm2_kernel<<<dim3(DD / GN, NROW / GM, 3 * 4), 256>>>(
            gq, gk, gv, NROW, DD, DD, 4, DD / 4, 1, p_part);
        EArgs eq{bq, eps_q, p_q};
        EArgs ek{bk, eps_k, p_k};
        EArgs ev{bv, eps_v, p_v};
        epi_simple_kernel<<<dim3(NROW * DD / 256, 3), 256>>>(
            eq, ek, ev, DD, NROW * DD, 4, 1, p_part);
    }
    // 2. attention
    attn_kernel<<<NROW, 256>>>(Kin, Vin, out + OFF_ATTNW, tptr);
    // 3. z = zattn @ Wo (+bo +eps_z), split-K 8, then fused epilogue+LN1
    {
        GArgs gw{p_zattn, Wo, bo, eps_z, p_z};
        gemm2_kernel<<<dim3(DD / GN, NROW / GM, 8), 256>>>(
            gw, gz0, gz0, NROW, DD, DD, 8, DD / 8, 0, p_part);
        epi_ln_kernel<<<NROW, 256>>>(p_part, 8, bo, eps_z, r, ln1_g, ln1_b,
                                     p_z, p_out1);
    }
    // 4. h = relu(out1 @ W1 + b1), split-K 2
    {
        GArgs gw{p_out1, W1, b1, nullptr, p_h};
        gemm2_kernel<<<dim3(DFF / GN, NROW / GM, 2), 256>>>(
            gw, gz0, gz0, NROW, DFF, DD, 2, DD / 2, 0, p_part);
        EArgs ef{b1, nullptr, p_h};
        epi_simple_kernel<<<dim3(NROW * DFF / 256, 1), 256>>>(
            ef, ef, ef, DFF, NROW * DFF, 2, 2, p_part);
    }
    // 5. f = h @ W2 + b2, split-K 8, fused epilogue+LN3 -> g_rr
    {
        GArgs gw{p_h, W2, b2, nullptr, p_rr};
        gemm2_kernel<<<dim3(DD / GN, NROW / GM, 8), 256>>>(
            gw, gz0, gz0, NROW, DD, DFF, 8, DFF / 8, 0, p_part);
        epi_ln_kernel<<<NROW, 256>>>(p_part, 8, b2, nullptr, p_out1,
                                     ln3_g, ln3_b, nullptr, p_rr);
    }
    // 6. predictions = r_ @ Wout + bout (direct write, 314 blocks)
    {
        GArgs gw{p_rr, Wout, bout, nullptr, p_pred};
        gemm2_kernel<<<dim3((VOC + GN - 1) / GN, NROW / GM, 1), 256>>>(
            gw, gz0, gz0, NROW, VOC, DD, 1, DD, 0, p_part);
    }
    // 7. softmax stats + w_sq
    rowsoftmax_kernel<<<NROW, 256>>>(x, out + OFF_WNEW);
    // 8. gumbel resampling indices + argmax
    particle_kernel<<<1, 128>>>(gumbel);
    // 9. vocab reductions
    vocab_reduce_kernel<<<dim3((VOC + 255) / 256, BB), 256>>>(
        out + OFF_AVGS, out + OFF_GAVG, out + OFF_MAXP);
    // 10. misc copies + gathers
    misc_kernel<<<NROW * DD / 256, 256>>>(r, eps_z, I, tptr, out);
    // 11. resample K and Vs
    resample_kernel<<<NROW * SS / 2, 256>>>(Kin, tptr, out);
}

// round 6
// speedup vs baseline: 1.3096x; 1.0272x over previous
#include <cuda_runtime.h>
#include <cuda_bf16.h>
#include <cstdint>
#include <cstdio>

// Problem constants
#define BB 8
#define PP 16
#define SS 512
#define DD 512
#define HH 8
#define DEPTH 64
#define DFF 2048
#define VOC 10000
#define NROW 128              // B*P
#define SIGMA 0.1f
#define LN_EPS 1e-6f

// Output offsets (float elements)
static const size_t OFF_R4    = 0;
static const size_t OFF_Z     = 65536;
static const size_t OFF_AVGS  = 131072;
static const size_t OFF_GAVG  = 211072;
static const size_t OFF_MAXP  = 291072;
static const size_t OFF_EPSZ  = 371072;
static const size_t OFF_ATTNW = 436608;
static const size_t OFF_K     = 502144;
static const size_t OFF_V     = 502144ULL + 33554432ULL;
static const size_t OFF_WNEW  = 67611008ULL;
static const size_t OFF_INEW  = 67611136ULL;

// ---------------- device scratch ----------------
__device__ float g_q[NROW * DD];
__device__ float g_k[NROW * DD];
__device__ float g_v[NROW * DD];
__device__ float g_zattn[NROW * DD];
__device__ float g_z[NROW * DD];
__device__ float g_out1[NROW * DD];
__device__ float g_h[NROW * DFF];
__device__ float g_rr[NROW * DD];
__device__ float g_pred[NROW * VOC];
__device__ float g_part[3 * 4 * NROW * DD * 4];   // partial buffer
__device__ float g_rowmax[NROW];
__device__ float g_rowrsum[NROW];
__device__ float g_wsq[NROW];
__device__ int   g_it[NROW];
__device__ int   g_argmax[BB];

// ---------------- packed f32x2 helpers ----------------
union F2U { float2 f; unsigned long long u; };

__device__ __forceinline__ unsigned long long fma2(unsigned long long a,
                                                   unsigned long long b,
                                                   unsigned long long c) {
    unsigned long long d;
    asm("fma.rn.f32x2 %0, %1, %2, %3;" : "=l"(d) : "l"(a), "l"(b), "l"(c));
    return d;
}

// ---------------- GEMM v3: double-buffered, 2 CTAs/SM ----------------
// C[M,N] = A[M,K] @ W[K,N]. Split-K over blockIdx.z; up to 3 fused GEMM instances.
// ksplit==1 -> direct write with bias/eps/relu; else raw partial into part[].
struct GArgs {
    const float* A;
    const float* W;
    const float* bias;
    const float* eps;
    float* C;
};

#define GM 64
#define GN 64
#define GK 32

__global__ __launch_bounds__(256, 2)
void gemm2_kernel(GArgs g0, GArgs g1, GArgs g2, int M, int N, int K,
                  int ksplit, int klen, int mode, float* part) {
    int z = blockIdx.z;
    int gi = z / ksplit, kz = z - gi * ksplit;
    GArgs g = (gi == 0) ? g0 : (gi == 1) ? g1 : g2;

    __shared__ float2 As2[2][GK][GM];   // duplicated {a,a}; 32 KB
    __shared__ float  Ws[2][GK][GN];    // 16 KB  (total 48 KB)

    int tid = threadIdx.x;
    int tx = tid & 15, ty = tid >> 4;
    int m0 = blockIdx.y * GM;
    int n0 = blockIdx.x * GN;
    int kbase = kz * klen;

    unsigned long long acc[4][2];
#pragma unroll
    for (int i = 0; i < 4; i++) { acc[i][0] = 0ULL; acc[i][1] = 0ULL; }

    int arow = tid >> 3, akq = tid & 7;   // A loader: rows arow, arow+32; 8 k-quads
    int wkk = tid >> 4, wnq = tid & 15;   // W loader: k rows wkk, wkk+16; 16 n-quads

    const float* Abase0 = &g.A[(size_t)(m0 + arow) * K + kbase + akq * 4];
    const float* Abase1 = &g.A[(size_t)(m0 + 32 + arow) * K + kbase + akq * 4];
    int ncol = n0 + wnq * 4;
    bool wok = (ncol < N);
    const float* Wbase0 = &g.W[(size_t)(kbase + wkk) * N + ncol];
    const float* Wbase1 = &g.W[(size_t)(kbase + 16 + wkk) * N + ncol];

    float4 ra0, ra1, rw0, rw1;

    // prologue: load tile 0
    ra0 = *(const float4*)(Abase0);
    ra1 = *(const float4*)(Abase1);
    rw0 = wok ? *(const float4*)(Wbase0) : make_float4(0.f, 0.f, 0.f, 0.f);
    rw1 = wok ? *(const float4*)(Wbase1) : make_float4(0.f, 0.f, 0.f, 0.f);
    // store tile 0 into buffer 0
    {
        As2[0][akq * 4 + 0][arow] = make_float2(ra0.x, ra0.x);
        As2[0][akq * 4 + 1][arow] = make_float2(ra0.y, ra0.y);
        As2[0][akq * 4 + 2][arow] = make_float2(ra0.z, ra0.z);
        As2[0][akq * 4 + 3][arow] = make_float2(ra0.w, ra0.w);
        As2[0][akq * 4 + 0][arow + 32] = make_float2(ra1.x, ra1.x);
        As2[0][akq * 4 + 1][arow + 32] = make_float2(ra1.y, ra1.y);
        As2[0][akq * 4 + 2][arow + 32] = make_float2(ra1.z, ra1.z);
        As2[0][akq * 4 + 3][arow + 32] = make_float2(ra1.w, ra1.w);
        *(float4*)&Ws[0][wkk][wnq * 4] = rw0;
        *(float4*)&Ws[0][16 + wkk][wnq * 4] = rw1;
    }
    __syncthreads();

    int nT = klen / GK;
    int buf = 0;
    for (int it = 0; it < nT; it++) {
        // prefetch next tile into registers (overlaps with compute below)
        if (it + 1 < nT) {
            int ko = (it + 1) * GK;
            ra0 = *(const float4*)(Abase0 + ko);
            ra1 = *(const float4*)(Abase1 + ko);
            rw0 = wok ? *(const float4*)(Wbase0 + (size_t)ko * N)
                      : make_float4(0.f, 0.f, 0.f, 0.f);
            rw1 = wok ? *(const float4*)(Wbase1 + (size_t)ko * N)
                      : make_float4(0.f, 0.f, 0.f, 0.f);
        }
        // compute current buffer
#pragma unroll
        for (int kk = 0; kk < GK; kk++) {
            F2U a0, a1, a2, a3, b0, b1;
            a0.f = As2[buf][kk][ty * 4 + 0];
            a1.f = As2[buf][kk][ty * 4 + 1];
            a2.f = As2[buf][kk][ty * 4 + 2];
            a3.f = As2[buf][kk][ty * 4 + 3];
            b0.f = *(const float2*)&Ws[buf][kk][tx * 4];
            b1.f = *(const float2*)&Ws[buf][kk][tx * 4 + 2];
            acc[0][0] = fma2(a0.u, b0.u, acc[0][0]);
            acc[0][1] = fma2(a0.u, b1.u, acc[0][1]);
            acc[1][0] = fma2(a1.u, b0.u, acc[1][0]);
            acc[1][1] = fma2(a1.u, b1.u, acc[1][1]);
            acc[2][0] = fma2(a2.u, b0.u, acc[2][0]);
            acc[2][1] = fma2(a2.u, b1.u, acc[2][1]);
            acc[3][0] = fma2(a3.u, b0.u, acc[3][0]);
            acc[3][1] = fma2(a3.u, b1.u, acc[3][1]);
        }
        // store prefetched tile into other buffer
        if (it + 1 < nT) {
            int nb = buf ^ 1;
            As2[nb][akq * 4 + 0][arow] = make_float2(ra0.x, ra0.x);
            As2[nb][akq * 4 + 1][arow] = make_float2(ra0.y, ra0.y);
            As2[nb][akq * 4 + 2][arow] = make_float2(ra0.z, ra0.z);
            As2[nb][akq * 4 + 3][arow] = make_float2(ra0.w, ra0.w);
            As2[nb][akq * 4 + 0][arow + 32] = make_float2(ra1.x, ra1.x);
            As2[nb][akq * 4 + 1][arow + 32] = make_float2(ra1.y, ra1.y);
            As2[nb][akq * 4 + 2][arow + 32] = make_float2(ra1.z, ra1.z);
            As2[nb][akq * 4 + 3][arow + 32] = make_float2(ra1.w, ra1.w);
            *(float4*)&Ws[nb][wkk][wnq * 4] = rw0;
            *(float4*)&Ws[nb][16 + wkk][wnq * 4] = rw1;
            __syncthreads();
        }
        buf ^= 1;
    }

    if (ksplit > 1) {
        float* P = part + (size_t)(gi * ksplit + kz) * M * N;
#pragma unroll
        for (int i = 0; i < 4; i++) {
            int row = m0 + ty * 4 + i;
#pragma unroll
            for (int jp = 0; jp < 2; jp++) {
                int col = n0 + tx * 4 + jp * 2;
                F2U t; t.u = acc[i][jp];
                if (col < N)     P[(size_t)row * N + col] = t.f.x;
                if (col + 1 < N) P[(size_t)row * N + col + 1] = t.f.y;
            }
        }
    } else {
#pragma unroll
        for (int i = 0; i < 4; i++) {
            int row = m0 + ty * 4 + i;
#pragma unroll
            for (int jp = 0; jp < 2; jp++) {
                int col = n0 + tx * 4 + jp * 2;
                F2U t; t.u = acc[i][jp];
                float vx = t.f.x, vy = t.f.y;
                if (col < N) {
                    float v = vx + g.bias[col];
                    if (mode == 1) v += SIGMA * g.eps[(size_t)row * N + col];
                    if (mode == 2) v = fmaxf(v, 0.0f);
                    g.C[(size_t)row * N + col] = v;
                }
                if (col + 1 < N) {
                    float v = vy + g.bias[col + 1];
                    if (mode == 1) v += SIGMA * g.eps[(size_t)row * N + col + 1];
                    if (mode == 2) v = fmaxf(v, 0.0f);
                    g.C[(size_t)row * N + col + 1] = v;
                }
            }
        }
    }
}

// ---------------- epilogue: sum partials + bias (+eps / relu) ----------------
struct EArgs { const float* bias; const float* eps; float* C; };

__global__ __launch_bounds__(256)
void epi_simple_kernel(EArgs e0, EArgs e1, EArgs e2, int N, int MN,
                       int ksplit, int mode, const float* part) {
    int gi = blockIdx.y;
    EArgs e = (gi == 0) ? e0 : (gi == 1) ? e1 : e2;
    int idx = blockIdx.x * 256 + threadIdx.x;
    if (idx >= MN) return;
    int col = idx % N;
    float v = e.bias[col];
    const float* P = part + (size_t)gi * ksplit * MN + idx;
    for (int kz = 0; kz < ksplit; kz++) v += P[(size_t)kz * MN];
    if (mode == 1) v += SIGMA * e.eps[idx];
    if (mode == 2) v = fmaxf(v, 0.0f);
    e.C[idx] = v;
}

// ---------------- epilogue with fused LayerNorm (N = DD = 512) ----------------
__global__ __launch_bounds__(256)
void epi_ln_kernel(const float* part, int ksplit,
                   const float* __restrict__ bias, const float* __restrict__ eps,
                   const float* __restrict__ add, const float* __restrict__ gam,
                   const float* __restrict__ bet, float* __restrict__ mid,
                   float* __restrict__ out) {
    int row = blockIdx.x;
    int tid = threadIdx.x;
    __shared__ float sh[8];
    __shared__ float s_mu, s_inv;

    int c0 = tid, c1 = tid + 256;
    float v0 = bias[c0], v1 = bias[c1];
    for (int kz = 0; kz < ksplit; kz++) {
        const float* P = part + (size_t)kz * NROW * DD + (size_t)row * DD;
        v0 += P[c0];
        v1 += P[c1];
    }
    if (eps) {
        v0 += SIGMA * eps[(size_t)row * DD + c0];
        v1 += SIGMA * eps[(size_t)row * DD + c1];
    }
    if (mid) {
        mid[(size_t)row * DD + c0] = v0;
        mid[(size_t)row * DD + c1] = v1;
    }
    float x0 = v0 + add[(size_t)row * DD + c0];
    float x1 = v1 + add[(size_t)row * DD + c1];

    float s = x0 + x1;
    float sq = x0 * x0 + x1 * x1;
#pragma unroll
    for (int o = 16; o; o >>= 1) {
        s  += __shfl_xor_sync(~0u, s, o);
        sq += __shfl_xor_sync(~0u, sq, o);
    }
    if ((tid & 31) == 0) sh[tid >> 5] = s;
    __syncthreads();
    if (tid == 0) {
        float t = 0;
        for (int i = 0; i < 8; i++) t += sh[i];
        s_mu = t / DD;
    }
    __syncthreads();
    if ((tid & 31) == 0) sh[tid >> 5] = sq;
    __syncthreads();
    if (tid == 0) {
        float t = 0;
        for (int i = 0; i < 8; i++) t += sh[i];
        float var = t / DD - s_mu * s_mu;
        s_inv = rsqrtf(var + LN_EPS);
    }
    __syncthreads();
    float mu = s_mu, inv = s_inv;
    out[(size_t)row * DD + c0] = (x0 - mu) * inv * gam[c0] + bet[c0];
    out[(size_t)row * DD + c1] = (x1 - mu) * inv * gam[c1] + bet[c1];
}

// ---------------- attention ----------------
__global__ __launch_bounds__(256)
void attn_kernel(const float* __restrict__ Kin, const float* __restrict__ Vin,
                 float* __restrict__ attnw, const int* __restrict__ tptr) {
    int t = *tptr;
    int tlen = t + 1;
    if (tlen > SS) tlen = SS;
    int bp = blockIdx.x;
    int tid = threadIdx.x;

    __shared__ float qs[DD];
    __shared__ float sc[HH][SS + 8];

    qs[tid] = g_q[bp * DD + tid];
    qs[tid + 256] = g_q[bp * DD + 256 + tid];
    __syncthreads();

    for (int idx = tid; idx < HH * tlen; idx += 256) {
        int h = idx / tlen;
        int s = idx - h * tlen;
        const float* kr = (s == t) ? &g_k[bp * DD]
                                   : &Kin[((size_t)bp * SS + s) * DD];
        const float4* k4 = (const float4*)(kr + h * DEPTH);
        const float4* q4 = (const float4*)(qs + h * DEPTH);
        float acc = 0.0f;
#pragma unroll
        for (int i = 0; i < DEPTH / 4; i++) {
            float4 kv = k4[i], qv = q4[i];
            acc += kv.x * qv.x + kv.y * qv.y + kv.z * qv.z + kv.w * qv.w;
        }
        sc[h][s] = acc * 0.125f;
    }
    __syncthreads();

    int wid = tid >> 5, lane = tid & 31;
    {
        float mx = -1e30f;
        for (int s = lane; s < tlen; s += 32) mx = fmaxf(mx, sc[wid][s]);
#pragma unroll
        for (int o = 16; o; o >>= 1) mx = fmaxf(mx, __shfl_xor_sync(~0u, mx, o));
        float sum = 0.0f;
        for (int s = lane; s < tlen; s += 32) {
            float e = __expf(sc[wid][s] - mx);
            sc[wid][s] = e;
            sum += e;
        }
#pragma unroll
        for (int o = 16; o; o >>= 1) sum += __shfl_xor_sync(~0u, sum, o);
        float r = 1.0f / sum;
        for (int s = lane; s < tlen; s += 32) sc[wid][s] *= r;
    }
    __syncthreads();

    for (int s = tid; s < SS; s += 256) {
        float v = 0.0f;
        if (s < tlen) {
#pragma unroll
            for (int h = 0; h < HH; h++) v += sc[h][s];
            v *= (1.0f / HH);
        }
        attnw[(size_t)bp * SS + s] = v;
    }

    int d0 = tid, d1 = tid + 256;
    int h0 = d0 >> 6, h1 = d1 >> 6;
    float acc0 = 0.0f, acc1 = 0.0f;
#pragma unroll 4
    for (int s = 0; s < tlen; s++) {
        const float* vr = (s == t) ? &g_v[bp * DD]
                                   : &Vin[((size_t)bp * SS + s) * DD];
        acc0 += sc[h0][s] * vr[d0];
        acc1 += sc[h1][s] * vr[d1];
    }
    g_zattn[bp * DD + d0] = acc0;
    g_zattn[bp * DD + d1] = acc1;
}

// ---------------- per-row softmax stats over VOC ----------------
__global__ __launch_bounds__(256)
void rowsoftmax_kernel(const int* __restrict__ x, float* __restrict__ wnew) {
    int row = blockIdx.x;
    const float* pr = g_pred + (size_t)row * VOC;
    int tid = threadIdx.x;
    __shared__ float sh[8];
    __shared__ float s_mx;

    float mx = -1e30f;
    for (int c = tid; c < VOC; c += 256) mx = fmaxf(mx, pr[c]);
#pragma unroll
    for (int o = 16; o; o >>= 1) mx = fmaxf(mx, __shfl_xor_sync(~0u, mx, o));
    if ((tid & 31) == 0) sh[tid >> 5] = mx;
    __syncthreads();
    if (tid == 0) {
        float m = sh[0];
        for (int i = 1; i < 8; i++) m = fmaxf(m, sh[i]);
        s_mx = m;
    }
    __syncthreads();
    mx = s_mx;
    float sum = 0.0f;
    for (int c = tid; c < VOC; c += 256) sum += __expf(pr[c] - mx);
#pragma unroll
    for (int o = 16; o; o >>= 1) sum += __shfl_xor_sync(~0u, sum, o);
    __syncthreads();
    if ((tid & 31) == 0) sh[tid >> 5] = sum;
    __syncthreads();
    if (tid == 0) {
        float sm = 0;
        for (int i = 0; i < 8; i++) sm += sh[i];
        g_rowmax[row] = mx;
        g_rowrsum[row] = 1.0f / sm;
        int b = row >> 4;
        float w = __expf(pr[x[b]] - mx) / sm;
        g_wsq[row] = w;
        wnew[row] = w;
    }
}

// ---------------- particle step ----------------
__global__ __launch_bounds__(128)
void particle_kernel(const float* __restrict__ gumbel) {
    int tid = threadIdx.x;
    int b = tid >> 4, p = tid & 15;
    __shared__ float lw[NROW];
    lw[tid] = logf(g_wsq[tid] + 1e-10f);
    __syncthreads();
    float best = -1e38f;
    int arg = 0;
    for (int j = 0; j < PP; j++) {
        float v = lw[b * PP + j] + gumbel[(b * PP + p) * PP + j];
        if (v > best) { best = v; arg = j; }
    }
    g_it[tid] = arg;
    if (p == 0) {
        float bw = g_wsq[b * PP];
        int a = 0;
        for (int j = 1; j < PP; j++)
            if (g_wsq[b * PP + j] > bw) { bw = g_wsq[b * PP + j]; a = j; }
        g_argmax[b] = a;
    }
}

// ---------------- vocab reductions ----------------
__global__ __launch_bounds__(256)
void vocab_reduce_kernel(float* __restrict__ avgs, float* __restrict__ gavg,
                         float* __restrict__ maxp) {
    int b = blockIdx.y;
    int c = blockIdx.x * 256 + threadIdx.x;
    if (c >= VOC) return;
    int am = g_argmax[b];
    float sp = 0.0f, ss = 0.0f, mp = 0.0f;
#pragma unroll
    for (int p = 0; p < PP; p++) {
        int row = b * PP + p;
        float v = g_pred[(size_t)row * VOC + c];
        sp += v;
        ss += __expf(v - g_rowmax[row]) * g_rowrsum[row];
        if (p == am) mp = v;
    }
    __stcs(&gavg[(size_t)b * VOC + c], sp * (1.0f / PP));
    __stcs(&avgs[(size_t)b * VOC + c], ss * (1.0f / PP));
    __stcs(&maxp[(size_t)b * VOC + c], mp);
}

// ---------------- misc copies / gathers ----------------
__global__ __launch_bounds__(256)
void misc_kernel(const float* __restrict__ r, const float* __restrict__ epsz,
                 const int* __restrict__ I, const int* __restrict__ tptr,
                 float* __restrict__ out) {
    int t = *tptr;
    int idx = blockIdx.x * 256 + threadIdx.x;
    out[OFF_R4 + idx] = r[idx];
    out[OFF_EPSZ + idx] = epsz[idx];
    int row = idx >> 9, d = idx & 511;
    int b = row >> 4;
    int i1 = g_it[row];
    out[OFF_Z + idx] = g_z[(b * PP + i1) * DD + d];
    int s = d;
    int val;
    if (s < t)      val = I[(b * PP + i1) * SS + s];
    else if (s == t) val = i1;
    else            val = I[idx];
    out[OFF_INEW + idx] = (float)val;
}

// ---------------- resample K and Vs (fused) ----------------
__global__ __launch_bounds__(256)
void resample_kernel(const float* __restrict__ Kin, const int* __restrict__ tptr,
                     float* __restrict__ out) {
    int t = *tptr;
    int tid = threadIdx.x;
    int rid = blockIdx.x * 2 + (tid >> 7);
    int d4 = tid & 127;
    int s = rid & 511;
    int bp = rid >> 9;
    int b = bp >> 4;
    size_t dst = (size_t)rid * DD + d4 * 4;
    if (s > t) {
        float4 v = __ldg(&((const float4*)&Kin[((size_t)bp * SS + s) * DD])[d4]);
        __stcs((float4*)&out[OFF_K + dst], v);
        __stcs((float4*)&out[OFF_V + dst], v);
    } else {
        int i1 = g_it[bp];
        int i2 = g_it[b * PP + i1];
        const float* sk = (s == t) ? &g_k[(b * PP + i1) * DD]
                                   : &Kin[(((size_t)(b * PP + i1)) * SS + s) * DD];
        const float* sv = (s == t) ? &g_k[(b * PP + i2) * DD]
                                   : &Kin[(((size_t)(b * PP + i2)) * SS + s) * DD];
        __stcs((float4*)&out[OFF_K + dst], ((const float4*)sk)[d4]);
        __stcs((float4*)&out[OFF_V + dst], ((const float4*)sv)[d4]);
    }
}

// ---------------- launch ----------------
extern "C" void kernel_launch(void* const* d_in, const int* in_sizes, int n_in,
                              void* d_out, int out_size) {
    (void)in_sizes; (void)n_in; (void)out_size;
    const float* r      = (const float*)d_in[0];
    const int*   x      = (const int*)d_in[1];
    const float* Kin    = (const float*)d_in[2];
    const float* Vin    = (const float*)d_in[3];
    const int*   I      = (const int*)d_in[5];
    const int*   tptr   = (const int*)d_in[6];
    const float* eps_q  = (const float*)d_in[7];
    const float* eps_k  = (const float*)d_in[8];
    const float* eps_v  = (const float*)d_in[9];
    const float* eps_z  = (const float*)d_in[10];
    const float* gumbel = (const float*)d_in[11];
    const float* Wq = (const float*)d_in[12];
    const float* bq = (const float*)d_in[13];
    const float* Wk = (const float*)d_in[14];
    const float* bk = (const float*)d_in[15];
    const float* Wv = (const float*)d_in[16];
    const float* bv = (const float*)d_in[17];
    const float* Wo = (const float*)d_in[18];
    const float* bo = (const float*)d_in[19];
    const float* ln1_g = (const float*)d_in[20];
    const float* ln1_b = (const float*)d_in[21];
    const float* ln3_g = (const float*)d_in[22];
    const float* ln3_b = (const float*)d_in[23];
    const float* W1 = (const float*)d_in[24];
    const float* b1 = (const float*)d_in[25];
    const float* W2 = (const float*)d_in[26];
    const float* b2 = (const float*)d_in[27];
    const float* Wout = (const float*)d_in[28];
    const float* bout = (const float*)d_in[29];
    float* out = (float*)d_out;

    float *p_q, *p_k, *p_v, *p_zattn, *p_z, *p_out1, *p_h, *p_rr, *p_pred, *p_part;
    cudaGetSymbolAddress((void**)&p_q, g_q);
    cudaGetSymbolAddress((void**)&p_k, g_k);
    cudaGetSymbolAddress((void**)&p_v, g_v);
    cudaGetSymbolAddress((void**)&p_zattn, g_zattn);
    cudaGetSymbolAddress((void**)&p_z, g_z);
    cudaGetSymbolAddress((void**)&p_out1, g_out1);
    cudaGetSymbolAddress((void**)&p_h, g_h);
    cudaGetSymbolAddress((void**)&p_rr, g_rr);
    cudaGetSymbolAddress((void**)&p_pred, g_pred);
    cudaGetSymbolAddress((void**)&p_part, g_part);

    GArgs gz0{nullptr, nullptr, nullptr, nullptr, nullptr};

    // 1. q,k,v projections: split-K 8 -> partials, then epilogue (+bias +eps)
    {
        GArgs gq{r, Wq, bq, eps_q, p_q};
        GArgs gk{r, Wk, bk, eps_k, p_k};
        GArgs gv{r, Wv, bv, eps_v, p_v};
        gemm2_kernel<<<dim3(DD / GN, NROW / GM, 3 * 8), 256>>>(
            gq, gk, gv, NROW, DD, DD, 8, DD / 8, 1, p_part);
        EArgs eq{bq, eps_q, p_q};
        EArgs ek{bk, eps_k, p_k};
        EArgs ev{bv, eps_v, p_v};
        epi_simple_kernel<<<dim3(NROW * DD / 256, 3), 256>>>(
            eq, ek, ev, DD, NROW * DD, 8, 1, p_part);
    }
    // 2. attention
    attn_kernel<<<NROW, 256>>>(Kin, Vin, out + OFF_ATTNW, tptr);
    // 3. z = zattn @ Wo (+bo +eps_z), split-K 16, then fused epilogue+LN1
    {
        GArgs gw{p_zattn, Wo, bo, eps_z, p_z};
        gemm2_kernel<<<dim3(DD / GN, NROW / GM, 16), 256>>>(
            gw, gz0, gz0, NROW, DD, DD, 16, DD / 16, 0, p_part);
        epi_ln_kernel<<<NROW, 256>>>(p_part, 16, bo, eps_z, r, ln1_g, ln1_b,
                                     p_z, p_out1);
    }
    // 4. h = relu(out1 @ W1 + b1), split-K 4
    {
        GArgs gw{p_out1, W1, b1, nullptr, p_h};
        gemm2_kernel<<<dim3(DFF / GN, NROW / GM, 4), 256>>>(
            gw, gz0, gz0, NROW, DFF, DD, 4, DD / 4, 0, p_part);
        EArgs ef{b1, nullptr, p_h};
        epi_simple_kernel<<<dim3(NROW * DFF / 256, 1), 256>>>(
            ef, ef, ef, DFF, NROW * DFF, 4, 2, p_part);
    }
    // 5. f = h @ W2 + b2, split-K 16, fused epilogue+LN3 -> g_rr
    {
        GArgs gw{p_h, W2, b2, nullptr, p_rr};
        gemm2_kernel<<<dim3(DD / GN, NROW / GM, 16), 256>>>(
            gw, gz0, gz0, NROW, DD, DFF, 16, DFF / 16, 0, p_part);
        epi_ln_kernel<<<NROW, 256>>>(p_part, 16, b2, nullptr, p_out1,
                                     ln3_g, ln3_b, nullptr, p_rr);
    }
    // 6. predictions = r_ @ Wout + bout (direct write, 314 blocks)
    {
        GArgs gw{p_rr, Wout, bout, nullptr, p_pred};
        gemm2_kernel<<<dim3((VOC + GN - 1) / GN, NROW / GM, 1), 256>>>(
            gw, gz0, gz0, NROW, VOC, DD, 1, DD, 0, p_part);
    }
    // 7. softmax stats + w_sq
    rowsoftmax_kernel<<<NROW, 256>>>(x, out + OFF_WNEW);
    // 8. gumbel resampling indices + argmax
    particle_kernel<<<1, 128>>>(gumbel);
    // 9. vocab reductions
    vocab_reduce_kernel<<<dim3((VOC + 255) / 256, BB), 256>>>(
        out + OFF_AVGS, out + OFF_GAVG, out + OFF_MAXP);
    // 10. misc copies + gathers
    misc_kernel<<<NROW * DD / 256, 256>>>(r, eps_z, I, tptr, out);
    // 11. resample K and Vs
    resample_kernel<<<NROW * SS / 2, 256>>>(Kin, tptr, out);
}